// round 15
// baseline (speedup 1.0000x reference)
#include <cuda_runtime.h>
#include <cuda_bf16.h>
#include <math.h>

#define N_   20000
#define E_   320000
#define ET_  (E_ + N_)      // 340000 with self loops
#define G_   512
#define IN_  74
#define ED_  12
#define HID_ 64
#define OUT_ 128
#define H_   4
#define HC1  (H_*HID_)      // 256
#define HC2  (H_*OUT_)      // 512
#define NB_  ((N_ + 255) / 256)   // 79 scan blocks

// ---------------- scratch (device globals; no allocations allowed) ----------
__device__ float g_h1lin[N_ * HC1];
__device__ float g_h1   [N_ * HC1];
__device__ float g_h2lin[N_ * HC2];
__device__ float g_as1[N_ * H_], g_ad1[N_ * H_];
__device__ float g_as2[N_ * H_], g_ad2[N_ * H_];
__device__ float g_ae1[ET_ * H_], g_ae2[ET_ * H_];
__device__ int   g_cnt[N_];
__device__ int   g_fill[N_];
__device__ int   g_rowptr[N_ + 1];
__device__ int   g_scan[N_];
__device__ int   g_bsum[NB_];
__device__ int   g_boff[NB_];
__device__ int   g_csr_src[ET_];
__device__ int   g_csr_eid[ET_];
__device__ float g_meansum[ED_];
__device__ float g_v1[ED_ * H_], g_v2[ED_ * H_];   // [d][h]
__device__ float g_self1[H_], g_self2[H_];
__device__ float g_gsum[G_ * OUT_];
__device__ float g_gcnt[G_];

// ---------------- init ----------------
__global__ void zero_kernel() {
    int i = blockIdx.x * blockDim.x + threadIdx.x;   // 65536 threads
    if (i < G_ * OUT_) g_gsum[i] = 0.f;
    if (i < G_)        g_gcnt[i] = 0.f;
    if (i < ED_)       g_meansum[i] = 0.f;
    if (i < N_)        g_cnt[i] = 0;
}

// ---------------- edge_attr mean (sum) ----------------
__global__ void ea_sum_kernel(const float* __restrict__ eattr) {
    __shared__ float sh[ED_];
    if (threadIdx.x < ED_) sh[threadIdx.x] = 0.f;
    __syncthreads();
    float loc[ED_];
#pragma unroll
    for (int d = 0; d < ED_; d++) loc[d] = 0.f;
    for (int e = blockIdx.x * blockDim.x + threadIdx.x; e < E_;
         e += gridDim.x * blockDim.x) {
#pragma unroll
        for (int d = 0; d < ED_; d++) loc[d] += eattr[e * ED_ + d];
    }
#pragma unroll
    for (int d = 0; d < ED_; d++) atomicAdd(&sh[d], loc[d]);
    __syncthreads();
    if (threadIdx.x < ED_) atomicAdd(&g_meansum[threadIdx.x], sh[threadIdx.x]);
}

// ---------------- fold We,a_e -> v[12][4]; self-loop constants --------------
__global__ void fold_v_kernel(const float* __restrict__ We1,
                              const float* __restrict__ aev1,  // [H,HID]
                              const float* __restrict__ We2,
                              const float* __restrict__ aev2)  // [H,OUT]
{
    int t = threadIdx.x;
    if (t < ED_ * H_) {
        int d = t / H_, h = t % H_;
        float s1 = 0.f;
        for (int c = 0; c < HID_; c++)
            s1 += We1[d * HC1 + h * HID_ + c] * aev1[h * HID_ + c];
        g_v1[t] = s1;
        float s2 = 0.f;
        for (int c = 0; c < OUT_; c++)
            s2 += We2[d * HC2 + h * OUT_ + c] * aev2[h * OUT_ + c];
        g_v2[t] = s2;
    }
    __syncthreads();
    if (t < H_) {
        const float invE = 1.f / (float)E_;
        float s1 = 0.f, s2 = 0.f;
        for (int d = 0; d < ED_; d++) {
            float m = g_meansum[d] * invE;
            s1 += m * g_v1[d * H_ + t];
            s2 += m * g_v2[d * H_ + t];
        }
        g_self1[t] = s1;
        g_self2[t] = s2;
    }
}

// ---------------- per-edge attention scores (both layers) -------------------
__global__ void edge_scores_kernel(const float* __restrict__ eattr) {
    int e = blockIdx.x * blockDim.x + threadIdx.x;
    if (e >= ET_) return;
    float s1[H_], s2[H_];
    if (e < E_) {
        float a[ED_];
#pragma unroll
        for (int d = 0; d < ED_; d++) a[d] = eattr[e * ED_ + d];
#pragma unroll
        for (int h = 0; h < H_; h++) {
            float t1 = 0.f, t2 = 0.f;
#pragma unroll
            for (int d = 0; d < ED_; d++) {
                t1 += a[d] * g_v1[d * H_ + h];
                t2 += a[d] * g_v2[d * H_ + h];
            }
            s1[h] = t1; s2[h] = t2;
        }
    } else {
#pragma unroll
        for (int h = 0; h < H_; h++) { s1[h] = g_self1[h]; s2[h] = g_self2[h]; }
    }
    ((float4*)g_ae1)[e] = make_float4(s1[0], s1[1], s1[2], s1[3]);
    ((float4*)g_ae2)[e] = make_float4(s2[0], s2[1], s2[2], s2[3]);
}

// ---------------- CSR build ----------------
__global__ void count_kernel(const int* __restrict__ ei) {
    int e = blockIdx.x * blockDim.x + threadIdx.x;
    if (e >= ET_) return;
    int dst = (e < E_) ? ei[E_ + e] : (e - E_);
    atomicAdd(&g_cnt[dst], 1);
}

// two-level scan: per-block inclusive scan + block totals
__global__ void scan_block_kernel() {
    int b = blockIdx.x, t = threadIdx.x;
    int i = b * 256 + t;
    int v = (i < N_) ? g_cnt[i] : 0;
    int lane = t & 31, w = t >> 5;
    int x = v;
#pragma unroll
    for (int off = 1; off < 32; off <<= 1) {
        int y = __shfl_up_sync(0xffffffffu, x, off);
        if (lane >= off) x += y;
    }
    __shared__ int ws[8];
    if (lane == 31) ws[w] = x;
    __syncthreads();
    if (t < 8) {
        int y = ws[t];
#pragma unroll
        for (int off = 1; off < 8; off <<= 1) {
            int z = __shfl_up_sync(0xffu, y, off);
            if (t >= off) y += z;
        }
        ws[t] = y;
    }
    __syncthreads();
    int incl = x + (w > 0 ? ws[w - 1] : 0);
    if (i < N_) g_scan[i] = incl;
    if (t == 255) g_bsum[b] = incl;
}

__global__ void scan_tops_kernel() {
    int t = threadIdx.x;        // 128 threads, NB_=79
    int v = (t < NB_) ? g_bsum[t] : 0;
    int lane = t & 31, w = t >> 5;
    int x = v;
#pragma unroll
    for (int off = 1; off < 32; off <<= 1) {
        int y = __shfl_up_sync(0xffffffffu, x, off);
        if (lane >= off) x += y;
    }
    __shared__ int ws[4];
    if (lane == 31) ws[w] = x;
    __syncthreads();
    if (t < 4) {
        int y = ws[t];
#pragma unroll
        for (int off = 1; off < 4; off <<= 1) {
            int z = __shfl_up_sync(0xfu, y, off);
            if (t >= off) y += z;
        }
        ws[t] = y;
    }
    __syncthreads();
    int incl = x + (w > 0 ? ws[w - 1] : 0);
    if (t < NB_) g_boff[t] = incl - v;   // exclusive
}

__global__ void scan_finish_kernel() {
    int i = blockIdx.x * blockDim.x + threadIdx.x;
    if (i >= N_) return;
    int r = g_boff[i >> 8] + g_scan[i];  // inclusive global prefix
    g_rowptr[i + 1] = r;
    g_fill[i] = r - g_cnt[i];
    if (i == 0) g_rowptr[0] = 0;
}

__global__ void scatter_kernel(const int* __restrict__ ei) {
    int e = blockIdx.x * blockDim.x + threadIdx.x;
    if (e >= ET_) return;
    int src, dst;
    if (e < E_) { src = ei[e]; dst = ei[E_ + e]; }
    else        { src = e - E_; dst = e - E_; }
    int p = atomicAdd(&g_fill[dst], 1);
    g_csr_src[p] = src;
    g_csr_eid[p] = e;
}

// ---------------- SGEMM 128x128x8, 8x8 microtile, staged prefetch -----------
template <bool VEC4A>
__global__ void __launch_bounds__(256, 2)
sgemm_kernel(const float* __restrict__ A, const float* __restrict__ B,
             float* __restrict__ C, int M, int N, int K)
{
    __shared__ float As[8][128];
    __shared__ float Bs[8][128];
    int tid = threadIdx.x;
    int tx = tid & 15, ty = tid >> 4;
    int row0 = blockIdx.y * 128, col0 = blockIdx.x * 128;

    // staging indices
    int am = tid >> 1, ak = (tid & 1) * 4;   // A: [128 rows][8 k] 4 elems/thread
    int br = tid >> 5, bc = (tid & 31) * 4;  // B: [8 k][128 cols] float4/thread

    float a_st[4];
    float4 b_st;
    int numT = (K + 7) / 8;

    float acc[8][8];
#pragma unroll
    for (int i = 0; i < 8; i++)
#pragma unroll
        for (int j = 0; j < 8; j++) acc[i][j] = 0.f;

    // initial load
    {
        int gm = row0 + am;
        if (VEC4A) {
            if (gm < M) {
                float4 t4 = *(const float4*)&A[(size_t)gm * K + ak];
                a_st[0] = t4.x; a_st[1] = t4.y; a_st[2] = t4.z; a_st[3] = t4.w;
            } else { a_st[0] = a_st[1] = a_st[2] = a_st[3] = 0.f; }
        } else {
#pragma unroll
            for (int j = 0; j < 4; j++) {
                int gk = ak + j;
                a_st[j] = (gm < M && gk < K) ? A[(size_t)gm * K + gk] : 0.f;
            }
        }
        if (br < K) b_st = *(const float4*)&B[(size_t)br * N + col0 + bc];
        else        b_st = make_float4(0.f, 0.f, 0.f, 0.f);
    }

    for (int t = 0; t < numT; t++) {
        // commit stage to smem
#pragma unroll
        for (int j = 0; j < 4; j++) As[ak + j][am] = a_st[j];
        *(float4*)&Bs[br][bc] = b_st;
        __syncthreads();

        // prefetch next tile while computing
        if (t + 1 < numT) {
            int k0 = (t + 1) * 8;
            int gm = row0 + am;
            if (VEC4A) {
                if (gm < M) {
                    float4 t4 = *(const float4*)&A[(size_t)gm * K + k0 + ak];
                    a_st[0] = t4.x; a_st[1] = t4.y; a_st[2] = t4.z; a_st[3] = t4.w;
                } else { a_st[0] = a_st[1] = a_st[2] = a_st[3] = 0.f; }
            } else {
#pragma unroll
                for (int j = 0; j < 4; j++) {
                    int gk = k0 + ak + j;
                    a_st[j] = (gm < M && gk < K) ? A[(size_t)gm * K + gk] : 0.f;
                }
            }
            int gk = k0 + br;
            if (gk < K) b_st = *(const float4*)&B[(size_t)gk * N + col0 + bc];
            else        b_st = make_float4(0.f, 0.f, 0.f, 0.f);
        }

#pragma unroll
        for (int k = 0; k < 8; k++) {
            float4 a0 = *(const float4*)&As[k][ty * 4];
            float4 a1 = *(const float4*)&As[k][64 + ty * 4];
            float4 b0 = *(const float4*)&Bs[k][tx * 4];
            float4 b1 = *(const float4*)&Bs[k][64 + tx * 4];
            float av[8] = {a0.x, a0.y, a0.z, a0.w, a1.x, a1.y, a1.z, a1.w};
            float bv[8] = {b0.x, b0.y, b0.z, b0.w, b1.x, b1.y, b1.z, b1.w};
#pragma unroll
            for (int i = 0; i < 8; i++)
#pragma unroll
                for (int j = 0; j < 8; j++) acc[i][j] += av[i] * bv[j];
        }
        __syncthreads();
    }

    // epilogue: rows {row0+ty*4+i, row0+64+ty*4+i}, cols {col0+tx*4.., col0+64+tx*4..}
#pragma unroll
    for (int ih = 0; ih < 2; ih++) {
#pragma unroll
        for (int i = 0; i < 4; i++) {
            int gm = row0 + ih * 64 + ty * 4 + i;
            if (gm >= M) continue;
            int r = ih * 4 + i;
            float4 o0 = make_float4(acc[r][0], acc[r][1], acc[r][2], acc[r][3]);
            float4 o1 = make_float4(acc[r][4], acc[r][5], acc[r][6], acc[r][7]);
            *(float4*)&C[(size_t)gm * N + col0 + tx * 4] = o0;
            *(float4*)&C[(size_t)gm * N + col0 + 64 + tx * 4] = o1;
        }
    }
}

// ---------------- node attention scores: as/ad [N,H] ------------------------
template <int HC, int C>
__global__ void node_scores_kernel(const float* __restrict__ hlin,
                                   const float* __restrict__ a_s,
                                   const float* __restrict__ a_d,
                                   float* __restrict__ as_out,
                                   float* __restrict__ ad_out)
{
    __shared__ float ss[HC];
    __shared__ float sd[HC];
    int n = blockIdx.x;
    int t = threadIdx.x;                  // blockDim == HC
    float h = hlin[(size_t)n * HC + t];
    ss[t] = h * a_s[t];
    sd[t] = h * a_d[t];
    __syncthreads();
#pragma unroll
    for (int off = C / 2; off > 0; off >>= 1) {
        if ((t & (C - 1)) < off) {
            ss[t] += ss[t + off];
            sd[t] += sd[t + off];
        }
        __syncthreads();
    }
    if ((t & (C - 1)) == 0) {
        as_out[n * H_ + t / C] = ss[t];
        ad_out[n * H_ + t / C] = sd[t];
    }
}

// ---------------- softmax + aggregate (one warp per dst node) ---------------
// single pass: softmax is shift invariant and scores are O(few), so no max pass
template <int HC, int C, bool MEANH>
__global__ void gat_aggregate_kernel(const float* __restrict__ hlin,
                                     const float* __restrict__ as_,
                                     const float* __restrict__ ad_,
                                     const float* __restrict__ ae_,
                                     const float* __restrict__ bias,
                                     float* __restrict__ out)
{
    constexpr int RV = HC / 128;          // float4 per lane (2 or 4)
    int warp = (blockIdx.x * blockDim.x + threadIdx.x) >> 5;
    int lane = threadIdx.x & 31;
    if (warp >= N_) return;
    int n = warp;
    int beg = g_rowptr[n], end = g_rowptr[n + 1];

    float4 adv = ((const float4*)ad_)[n];

    float acc[RV][4];
#pragma unroll
    for (int r = 0; r < RV; r++)
#pragma unroll
        for (int i = 0; i < 4; i++) acc[r][i] = 0.f;
    float ssum[H_] = {0.f, 0.f, 0.f, 0.f};

    for (int i = beg; i < end; i++) {
        int s = g_csr_src[i];
        int e = g_csr_eid[i];
        float4 av = ((const float4*)as_)[s];
        float4 ev = ((const float4*)ae_)[e];
        float ex[H_];
        {
            float a0 = av.x + adv.x + ev.x; a0 = fmaxf(a0, 0.2f * a0);
            float a1 = av.y + adv.y + ev.y; a1 = fmaxf(a1, 0.2f * a1);
            float a2 = av.z + adv.z + ev.z; a2 = fmaxf(a2, 0.2f * a2);
            float a3 = av.w + adv.w + ev.w; a3 = fmaxf(a3, 0.2f * a3);
            ex[0] = __expf(a0); ex[1] = __expf(a1);
            ex[2] = __expf(a2); ex[3] = __expf(a3);
            ssum[0] += ex[0]; ssum[1] += ex[1];
            ssum[2] += ex[2]; ssum[3] += ex[3];
        }
        const float4* hp = (const float4*)hlin + (size_t)s * (HC / 4);
#pragma unroll
        for (int r = 0; r < RV; r++) {
            float4 v = hp[lane + 32 * r];
            float w;
            if (C == 128) w = ex[r];                       // head == r
            else          w = (lane < 16) ? ex[2 * r] : ex[2 * r + 1];
            acc[r][0] += w * v.x; acc[r][1] += w * v.y;
            acc[r][2] += w * v.z; acc[r][3] += w * v.w;
        }
    }

    if (!MEANH) {
        // concat heads: out[n, 4*(lane+32r)+i] = relu(acc/s + b)
#pragma unroll
        for (int r = 0; r < RV; r++) {
            float sden = (C == 128) ? ssum[r]
                       : ((lane < 16) ? ssum[2 * r] : ssum[2 * r + 1]);
            float inv = 1.f / (sden + 1e-16f);
            float4 b4 = ((const float4*)bias)[lane + 32 * r];
            float4 o;
            o.x = fmaxf(acc[r][0] * inv + b4.x, 0.f);
            o.y = fmaxf(acc[r][1] * inv + b4.y, 0.f);
            o.z = fmaxf(acc[r][2] * inv + b4.z, 0.f);
            o.w = fmaxf(acc[r][3] * inv + b4.w, 0.f);
            ((float4*)out)[(size_t)n * (HC / 4) + lane + 32 * r] = o;
        }
    } else {
        // mean over heads: lane owns cols 4*lane..4*lane+3 of every head
        float v[4] = {0.f, 0.f, 0.f, 0.f};
#pragma unroll
        for (int r = 0; r < RV; r++) {
            float inv = 1.f / (ssum[r] + 1e-16f);
            v[0] += acc[r][0] * inv; v[1] += acc[r][1] * inv;
            v[2] += acc[r][2] * inv; v[3] += acc[r][3] * inv;
        }
        float4 b4 = ((const float4*)bias)[lane];
        float4 o;
        o.x = fmaxf(v[0] * 0.25f + b4.x, 0.f);
        o.y = fmaxf(v[1] * 0.25f + b4.y, 0.f);
        o.z = fmaxf(v[2] * 0.25f + b4.z, 0.f);
        o.w = fmaxf(v[3] * 0.25f + b4.w, 0.f);
        ((float4*)out)[(size_t)n * (OUT_ / 4) + lane] = o;
    }
}

// ---------------- pooling ----------------
__global__ void pool_accum_kernel(const float* __restrict__ h2,
                                  const int* __restrict__ batch)
{
    int n = blockIdx.x;
    int c = threadIdx.x;                  // 128
    int g = batch[n];
    atomicAdd(&g_gsum[g * OUT_ + c], h2[(size_t)n * OUT_ + c]);
    if (c == 0) atomicAdd(&g_gcnt[g], 1.f);
}

__global__ void pool_final_kernel(float* __restrict__ out) {
    int i = blockIdx.x * blockDim.x + threadIdx.x;   // G_*OUT_
    if (i >= G_ * OUT_) return;
    float cnt = fmaxf(g_gcnt[i / OUT_], 1.f);
    out[(size_t)N_ * OUT_ + i] = g_gsum[i] / cnt;
}

// ---------------- launcher ----------------
extern "C" void kernel_launch(void* const* d_in, const int* in_sizes, int n_in,
                              void* d_out, int out_size)
{
    const float* x       = (const float*)d_in[0];
    const float* eattr   = (const float*)d_in[1];
    const float* W1      = (const float*)d_in[2];
    const float* a_src1  = (const float*)d_in[3];
    const float* a_dst1  = (const float*)d_in[4];
    const float* We1     = (const float*)d_in[5];
    const float* a_edge1 = (const float*)d_in[6];
    const float* b1      = (const float*)d_in[7];
    const float* W2      = (const float*)d_in[8];
    const float* a_src2  = (const float*)d_in[9];
    const float* a_dst2  = (const float*)d_in[10];
    const float* We2     = (const float*)d_in[11];
    const float* a_edge2 = (const float*)d_in[12];
    const float* b2      = (const float*)d_in[13];
    const int*   eindex  = (const int*)d_in[14];
    const int*   batch   = (const int*)d_in[15];
    float* out = (float*)d_out;

    float *h1lin, *h1, *h2lin;
    cudaGetSymbolAddress((void**)&h1lin, g_h1lin);
    cudaGetSymbolAddress((void**)&h1,    g_h1);
    cudaGetSymbolAddress((void**)&h2lin, g_h2lin);
    float *as1p, *ad1p, *as2p, *ad2p, *ae1p, *ae2p;
    cudaGetSymbolAddress((void**)&as1p, g_as1);
    cudaGetSymbolAddress((void**)&ad1p, g_ad1);
    cudaGetSymbolAddress((void**)&as2p, g_as2);
    cudaGetSymbolAddress((void**)&ad2p, g_ad2);
    cudaGetSymbolAddress((void**)&ae1p, g_ae1);
    cudaGetSymbolAddress((void**)&ae2p, g_ae2);

    // 0) init
    zero_kernel<<<256, 256>>>();
    // 1) edge-attr mean + fold tiny matrices
    ea_sum_kernel<<<256, 256>>>(eattr);
    fold_v_kernel<<<1, 64>>>(We1, a_edge1, We2, a_edge2);
    // 2) CSR build (two-level scan)
    count_kernel<<<(ET_ + 255) / 256, 256>>>(eindex);
    scan_block_kernel<<<NB_, 256>>>();
    scan_tops_kernel<<<1, 128>>>();
    scan_finish_kernel<<<(N_ + 255) / 256, 256>>>();
    scatter_kernel<<<(ET_ + 255) / 256, 256>>>(eindex);
    // 3) per-edge scores (both layers)
    edge_scores_kernel<<<(ET_ + 255) / 256, 256>>>(eattr);
    // 4) layer 1
    {
        dim3 grid(HC1 / 128, (N_ + 127) / 128);
        sgemm_kernel<false><<<grid, 256>>>(x, W1, h1lin, N_, HC1, IN_);
    }
    node_scores_kernel<HC1, HID_><<<N_, HC1>>>(h1lin, a_src1, a_dst1, as1p, ad1p);
    gat_aggregate_kernel<HC1, HID_, false>
        <<<(N_ * 32 + 255) / 256, 256>>>(h1lin, as1p, ad1p, ae1p, b1, h1);
    // 5) layer 2
    {
        dim3 grid(HC2 / 128, (N_ + 127) / 128);
        sgemm_kernel<true><<<grid, 256>>>(h1, W2, h2lin, N_, HC2, HC1);
    }
    node_scores_kernel<HC2, OUT_><<<N_, HC2>>>(h2lin, a_src2, a_dst2, as2p, ad2p);
    gat_aggregate_kernel<HC2, OUT_, true>
        <<<(N_ * 32 + 255) / 256, 256>>>(h2lin, as2p, ad2p, ae2p, b2, out);
    // 6) graph pooling
    pool_accum_kernel<<<N_, OUT_>>>(out, batch);
    pool_final_kernel<<<(G_ * OUT_ + 255) / 256, 256>>>(out);
}

// round 16
// speedup vs baseline: 1.1853x; 1.1853x over previous
#include <cuda_runtime.h>
#include <cuda_bf16.h>
#include <math.h>

#define N_   20000
#define E_   320000
#define ET_  (E_ + N_)      // 340000 with self loops
#define G_   512
#define IN_  74
#define ED_  12
#define HID_ 64
#define OUT_ 128
#define H_   4
#define HC1  (H_*HID_)      // 256
#define HC2  (H_*OUT_)      // 512
#define NB_  ((N_ + 255) / 256)   // 79 scan blocks

// ---------------- scratch (device globals; no allocations allowed) ----------
__device__ float g_h1lin[N_ * HC1];
__device__ float g_h1   [N_ * HC1];
__device__ float g_h2lin[N_ * HC2];
__device__ float g_as1[N_ * H_], g_ad1[N_ * H_];
__device__ float g_as2[N_ * H_], g_ad2[N_ * H_];
__device__ float g_ae1[ET_ * H_], g_ae2[ET_ * H_];
__device__ int   g_cnt[N_];
__device__ int   g_fill[N_];
__device__ int   g_rowptr[N_ + 1];
__device__ int   g_scan[N_];
__device__ int   g_bsum[NB_];
__device__ int   g_boff[NB_];
__device__ int   g_csr_src[ET_];
__device__ int   g_csr_eid[ET_];
__device__ float g_meansum[ED_];
__device__ float g_v1[ED_ * H_], g_v2[ED_ * H_];   // [d][h]
__device__ float g_self1[H_], g_self2[H_];
__device__ float g_gsum[G_ * OUT_];
__device__ float g_gcnt[G_];

// ---------------- packed fp32x2 FMA helpers ----------------
__device__ __forceinline__ void ffma2(unsigned long long& c,
                                      unsigned long long a,
                                      unsigned long long b) {
    asm("fma.rn.f32x2 %0, %1, %2, %0;" : "+l"(c) : "l"(a), "l"(b));
}
__device__ __forceinline__ unsigned long long pack_dup(float a) {
    unsigned long long r;
    unsigned int ai = __float_as_uint(a);
    asm("mov.b64 %0, {%1, %1};" : "=l"(r) : "r"(ai));
    return r;
}
__device__ __forceinline__ void unpack2(unsigned long long v, float& lo, float& hi) {
    unsigned int l, h;
    asm("mov.b64 {%0, %1}, %2;" : "=r"(l), "=r"(h) : "l"(v));
    lo = __uint_as_float(l);
    hi = __uint_as_float(h);
}

// ---------------- init ----------------
__global__ void zero_kernel() {
    int i = blockIdx.x * blockDim.x + threadIdx.x;   // 65536 threads
    if (i < G_ * OUT_) g_gsum[i] = 0.f;
    if (i < G_)        g_gcnt[i] = 0.f;
    if (i < ED_)       g_meansum[i] = 0.f;
    if (i < N_)        g_cnt[i] = 0;
}

// ---------------- edge_attr mean (sum) ----------------
__global__ void ea_sum_kernel(const float* __restrict__ eattr) {
    __shared__ float sh[ED_];
    if (threadIdx.x < ED_) sh[threadIdx.x] = 0.f;
    __syncthreads();
    float loc[ED_];
#pragma unroll
    for (int d = 0; d < ED_; d++) loc[d] = 0.f;
    for (int e = blockIdx.x * blockDim.x + threadIdx.x; e < E_;
         e += gridDim.x * blockDim.x) {
#pragma unroll
        for (int d = 0; d < ED_; d++) loc[d] += eattr[e * ED_ + d];
    }
#pragma unroll
    for (int d = 0; d < ED_; d++) atomicAdd(&sh[d], loc[d]);
    __syncthreads();
    if (threadIdx.x < ED_) atomicAdd(&g_meansum[threadIdx.x], sh[threadIdx.x]);
}

// ---------------- fold We,a_e -> v[12][4]; self-loop constants --------------
__global__ void fold_v_kernel(const float* __restrict__ We1,
                              const float* __restrict__ aev1,  // [H,HID]
                              const float* __restrict__ We2,
                              const float* __restrict__ aev2)  // [H,OUT]
{
    int t = threadIdx.x;
    if (t < ED_ * H_) {
        int d = t / H_, h = t % H_;
        float s1 = 0.f;
        for (int c = 0; c < HID_; c++)
            s1 += We1[d * HC1 + h * HID_ + c] * aev1[h * HID_ + c];
        g_v1[t] = s1;
        float s2 = 0.f;
        for (int c = 0; c < OUT_; c++)
            s2 += We2[d * HC2 + h * OUT_ + c] * aev2[h * OUT_ + c];
        g_v2[t] = s2;
    }
    __syncthreads();
    if (t < H_) {
        const float invE = 1.f / (float)E_;
        float s1 = 0.f, s2 = 0.f;
        for (int d = 0; d < ED_; d++) {
            float m = g_meansum[d] * invE;
            s1 += m * g_v1[d * H_ + t];
            s2 += m * g_v2[d * H_ + t];
        }
        g_self1[t] = s1;
        g_self2[t] = s2;
    }
}

// ---------------- per-edge attention scores (both layers) -------------------
__global__ void edge_scores_kernel(const float* __restrict__ eattr) {
    int e = blockIdx.x * blockDim.x + threadIdx.x;
    if (e >= ET_) return;
    float s1[H_], s2[H_];
    if (e < E_) {
        float a[ED_];
#pragma unroll
        for (int d = 0; d < ED_; d++) a[d] = eattr[e * ED_ + d];
#pragma unroll
        for (int h = 0; h < H_; h++) {
            float t1 = 0.f, t2 = 0.f;
#pragma unroll
            for (int d = 0; d < ED_; d++) {
                t1 += a[d] * g_v1[d * H_ + h];
                t2 += a[d] * g_v2[d * H_ + h];
            }
            s1[h] = t1; s2[h] = t2;
        }
    } else {
#pragma unroll
        for (int h = 0; h < H_; h++) { s1[h] = g_self1[h]; s2[h] = g_self2[h]; }
    }
    ((float4*)g_ae1)[e] = make_float4(s1[0], s1[1], s1[2], s1[3]);
    ((float4*)g_ae2)[e] = make_float4(s2[0], s2[1], s2[2], s2[3]);
}

// ---------------- CSR build ----------------
__global__ void count_kernel(const int* __restrict__ ei) {
    int e = blockIdx.x * blockDim.x + threadIdx.x;
    if (e >= ET_) return;
    int dst = (e < E_) ? ei[E_ + e] : (e - E_);
    atomicAdd(&g_cnt[dst], 1);
}

// two-level scan: per-block inclusive scan + block totals
__global__ void scan_block_kernel() {
    int b = blockIdx.x, t = threadIdx.x;
    int i = b * 256 + t;
    int v = (i < N_) ? g_cnt[i] : 0;
    int lane = t & 31, w = t >> 5;
    int x = v;
#pragma unroll
    for (int off = 1; off < 32; off <<= 1) {
        int y = __shfl_up_sync(0xffffffffu, x, off);
        if (lane >= off) x += y;
    }
    __shared__ int ws[8];
    if (lane == 31) ws[w] = x;
    __syncthreads();
    if (t < 8) {
        int y = ws[t];
#pragma unroll
        for (int off = 1; off < 8; off <<= 1) {
            int z = __shfl_up_sync(0xffu, y, off);
            if (t >= off) y += z;
        }
        ws[t] = y;
    }
    __syncthreads();
    int incl = x + (w > 0 ? ws[w - 1] : 0);
    if (i < N_) g_scan[i] = incl;
    if (t == 255) g_bsum[b] = incl;
}

__global__ void scan_tops_kernel() {
    int t = threadIdx.x;        // 128 threads, NB_=79
    int v = (t < NB_) ? g_bsum[t] : 0;
    int lane = t & 31, w = t >> 5;
    int x = v;
#pragma unroll
    for (int off = 1; off < 32; off <<= 1) {
        int y = __shfl_up_sync(0xffffffffu, x, off);
        if (lane >= off) x += y;
    }
    __shared__ int ws[4];
    if (lane == 31) ws[w] = x;
    __syncthreads();
    if (t < 4) {
        int y = ws[t];
#pragma unroll
        for (int off = 1; off < 4; off <<= 1) {
            int z = __shfl_up_sync(0xfu, y, off);
            if (t >= off) y += z;
        }
        ws[t] = y;
    }
    __syncthreads();
    int incl = x + (w > 0 ? ws[w - 1] : 0);
    if (t < NB_) g_boff[t] = incl - v;   // exclusive
}

__global__ void scan_finish_kernel() {
    int i = blockIdx.x * blockDim.x + threadIdx.x;
    if (i >= N_) return;
    int r = g_boff[i >> 8] + g_scan[i];  // inclusive global prefix
    g_rowptr[i + 1] = r;
    g_fill[i] = r - g_cnt[i];
    if (i == 0) g_rowptr[0] = 0;
}

__global__ void scatter_kernel(const int* __restrict__ ei) {
    int e = blockIdx.x * blockDim.x + threadIdx.x;
    if (e >= ET_) return;
    int src, dst;
    if (e < E_) { src = ei[e]; dst = ei[E_ + e]; }
    else        { src = e - E_; dst = e - E_; }
    int p = atomicAdd(&g_fill[dst], 1);
    g_csr_src[p] = src;
    g_csr_eid[p] = e;
}

// ---------------- SGEMM 128x128x8, 8x8 microtile, f32x2 packed FMA ----------
template <bool VEC4A>
__global__ void __launch_bounds__(256, 2)
sgemm_kernel(const float* __restrict__ A, const float* __restrict__ B,
             float* __restrict__ C, int M, int N, int K)
{
    __shared__ __align__(16) float As[8][128];
    __shared__ __align__(16) float Bs[8][128];
    int tid = threadIdx.x;
    int tx = tid & 15, ty = tid >> 4;
    int row0 = blockIdx.y * 128, col0 = blockIdx.x * 128;

    // staging indices
    int am = tid >> 1, ak = (tid & 1) * 4;   // A: [128 rows][8 k] 4 elems/thread
    int br = tid >> 5, bc = (tid & 31) * 4;  // B: [8 k][128 cols] float4/thread

    float a_st[4];
    float4 b_st;
    int numT = (K + 7) / 8;

    // acc pairs: acc2[i][q] holds C columns {2q, 2q+1} of the 8-wide j range
    unsigned long long acc2[8][4];
#pragma unroll
    for (int i = 0; i < 8; i++)
#pragma unroll
        for (int q = 0; q < 4; q++) acc2[i][q] = 0ull;  // (0.f, 0.f)

    // initial load
    {
        int gm = row0 + am;
        if (VEC4A) {
            if (gm < M) {
                float4 t4 = *(const float4*)&A[(size_t)gm * K + ak];
                a_st[0] = t4.x; a_st[1] = t4.y; a_st[2] = t4.z; a_st[3] = t4.w;
            } else { a_st[0] = a_st[1] = a_st[2] = a_st[3] = 0.f; }
        } else {
#pragma unroll
            for (int j = 0; j < 4; j++) {
                int gk = ak + j;
                a_st[j] = (gm < M && gk < K) ? A[(size_t)gm * K + gk] : 0.f;
            }
        }
        if (br < K) b_st = *(const float4*)&B[(size_t)br * N + col0 + bc];
        else        b_st = make_float4(0.f, 0.f, 0.f, 0.f);
    }

    for (int t = 0; t < numT; t++) {
        // commit stage to smem
#pragma unroll
        for (int j = 0; j < 4; j++) As[ak + j][am] = a_st[j];
        *(float4*)&Bs[br][bc] = b_st;
        __syncthreads();

        // prefetch next tile while computing
        if (t + 1 < numT) {
            int k0 = (t + 1) * 8;
            int gm = row0 + am;
            if (VEC4A) {
                if (gm < M) {
                    float4 t4 = *(const float4*)&A[(size_t)gm * K + k0 + ak];
                    a_st[0] = t4.x; a_st[1] = t4.y; a_st[2] = t4.z; a_st[3] = t4.w;
                } else { a_st[0] = a_st[1] = a_st[2] = a_st[3] = 0.f; }
            } else {
#pragma unroll
                for (int j = 0; j < 4; j++) {
                    int gk = k0 + ak + j;
                    a_st[j] = (gm < M && gk < K) ? A[(size_t)gm * K + gk] : 0.f;
                }
            }
            int gk = k0 + br;
            if (gk < K) b_st = *(const float4*)&B[(size_t)gk * N + col0 + bc];
            else        b_st = make_float4(0.f, 0.f, 0.f, 0.f);
        }

#pragma unroll
        for (int k = 0; k < 8; k++) {
            float4 a0 = *(const float4*)&As[k][ty * 4];
            float4 a1 = *(const float4*)&As[k][64 + ty * 4];
            // B pairs come straight out of shared as 64-bit lanes
            ulonglong2 b01 = *(const ulonglong2*)&Bs[k][tx * 4];
            ulonglong2 b23 = *(const ulonglong2*)&Bs[k][64 + tx * 4];
            float av[8] = {a0.x, a0.y, a0.z, a0.w, a1.x, a1.y, a1.z, a1.w};
#pragma unroll
            for (int i = 0; i < 8; i++) {
                unsigned long long ap = pack_dup(av[i]);
                ffma2(acc2[i][0], ap, b01.x);
                ffma2(acc2[i][1], ap, b01.y);
                ffma2(acc2[i][2], ap, b23.x);
                ffma2(acc2[i][3], ap, b23.y);
            }
        }
        __syncthreads();
    }

    // epilogue
#pragma unroll
    for (int ih = 0; ih < 2; ih++) {
#pragma unroll
        for (int i = 0; i < 4; i++) {
            int gm = row0 + ih * 64 + ty * 4 + i;
            if (gm >= M) continue;
            int r = ih * 4 + i;
            float4 o0, o1;
            unpack2(acc2[r][0], o0.x, o0.y);
            unpack2(acc2[r][1], o0.z, o0.w);
            unpack2(acc2[r][2], o1.x, o1.y);
            unpack2(acc2[r][3], o1.z, o1.w);
            *(float4*)&C[(size_t)gm * N + col0 + tx * 4] = o0;
            *(float4*)&C[(size_t)gm * N + col0 + 64 + tx * 4] = o1;
        }
    }
}

// ---------------- node attention scores: warp per node, shuffle reduce ------
template <int HC, int C>
__global__ void node_scores_kernel(const float* __restrict__ hlin,
                                   const float* __restrict__ a_s,
                                   const float* __restrict__ a_d,
                                   float* __restrict__ as_out,
                                   float* __restrict__ ad_out)
{
    constexpr int RV = HC / 128;          // float4 per lane
    int warp = (blockIdx.x * blockDim.x + threadIdx.x) >> 5;
    int lane = threadIdx.x & 31;
    if (warp >= N_) return;
    const float4* hp = (const float4*)(hlin + (size_t)warp * HC);

    float ps[RV], pd[RV];
#pragma unroll
    for (int r = 0; r < RV; r++) {
        int u = lane + 32 * r;
        float4 h = hp[u];
        float4 s4 = ((const float4*)a_s)[u];
        float4 d4 = ((const float4*)a_d)[u];
        ps[r] = h.x * s4.x + h.y * s4.y + h.z * s4.z + h.w * s4.w;
        pd[r] = h.x * d4.x + h.y * d4.y + h.z * d4.z + h.w * d4.w;
    }

    if (C == 128) {
        // head == r: full-warp reduce each r
#pragma unroll
        for (int off = 16; off > 0; off >>= 1)
#pragma unroll
            for (int r = 0; r < RV; r++) {
                ps[r] += __shfl_xor_sync(0xffffffffu, ps[r], off);
                pd[r] += __shfl_xor_sync(0xffffffffu, pd[r], off);
            }
        if (lane == 0) {
            ((float4*)as_out)[warp] = make_float4(ps[0], ps[1], ps[2], ps[3]);
            ((float4*)ad_out)[warp] = make_float4(pd[0], pd[1], pd[2], pd[3]);
        }
    } else {
        // C==64, RV==2: head = (lane>>4) + 2r; reduce within 16-lane halves
#pragma unroll
        for (int off = 8; off > 0; off >>= 1)
#pragma unroll
            for (int r = 0; r < RV; r++) {
                ps[r] += __shfl_xor_sync(0xffffffffu, ps[r], off);
                pd[r] += __shfl_xor_sync(0xffffffffu, pd[r], off);
            }
        // lanes 0..15 hold heads {0,2}; lanes 16..31 hold heads {1,3}
        float s1 = __shfl_sync(0xffffffffu, ps[0], 16);
        float s3 = __shfl_sync(0xffffffffu, ps[1], 16);
        float d1 = __shfl_sync(0xffffffffu, pd[0], 16);
        float d3 = __shfl_sync(0xffffffffu, pd[1], 16);
        if (lane == 0) {
            ((float4*)as_out)[warp] = make_float4(ps[0], s1, ps[1], s3);
            ((float4*)ad_out)[warp] = make_float4(pd[0], d1, pd[1], d3);
        }
    }
}

// ---------------- softmax + aggregate (one warp per dst node) ---------------
// single pass: softmax is shift invariant and scores are O(few), so no max pass
template <int HC, int C, bool MEANH>
__global__ void gat_aggregate_kernel(const float* __restrict__ hlin,
                                     const float* __restrict__ as_,
                                     const float* __restrict__ ad_,
                                     const float* __restrict__ ae_,
                                     const float* __restrict__ bias,
                                     float* __restrict__ out)
{
    constexpr int RV = HC / 128;          // float4 per lane (2 or 4)
    int warp = (blockIdx.x * blockDim.x + threadIdx.x) >> 5;
    int lane = threadIdx.x & 31;
    if (warp >= N_) return;
    int n = warp;
    int beg = g_rowptr[n], end = g_rowptr[n + 1];

    float4 adv = ((const float4*)ad_)[n];

    float acc[RV][4];
#pragma unroll
    for (int r = 0; r < RV; r++)
#pragma unroll
        for (int i = 0; i < 4; i++) acc[r][i] = 0.f;
    float ssum[H_] = {0.f, 0.f, 0.f, 0.f};

    for (int i = beg; i < end; i++) {
        int s = g_csr_src[i];
        int e = g_csr_eid[i];
        float4 av = ((const float4*)as_)[s];
        float4 ev = ((const float4*)ae_)[e];
        float ex[H_];
        {
            float a0 = av.x + adv.x + ev.x; a0 = fmaxf(a0, 0.2f * a0);
            float a1 = av.y + adv.y + ev.y; a1 = fmaxf(a1, 0.2f * a1);
            float a2 = av.z + adv.z + ev.z; a2 = fmaxf(a2, 0.2f * a2);
            float a3 = av.w + adv.w + ev.w; a3 = fmaxf(a3, 0.2f * a3);
            ex[0] = __expf(a0); ex[1] = __expf(a1);
            ex[2] = __expf(a2); ex[3] = __expf(a3);
            ssum[0] += ex[0]; ssum[1] += ex[1];
            ssum[2] += ex[2]; ssum[3] += ex[3];
        }
        const float4* hp = (const float4*)hlin + (size_t)s * (HC / 4);
#pragma unroll
        for (int r = 0; r < RV; r++) {
            float4 v = hp[lane + 32 * r];
            float w;
            if (C == 128) w = ex[r];                       // head == r
            else          w = (lane < 16) ? ex[2 * r] : ex[2 * r + 1];
            acc[r][0] += w * v.x; acc[r][1] += w * v.y;
            acc[r][2] += w * v.z; acc[r][3] += w * v.w;
        }
    }

    if (!MEANH) {
        // concat heads: out[n, 4*(lane+32r)+i] = relu(acc/s + b)
#pragma unroll
        for (int r = 0; r < RV; r++) {
            float sden = (C == 128) ? ssum[r]
                       : ((lane < 16) ? ssum[2 * r] : ssum[2 * r + 1]);
            float inv = 1.f / (sden + 1e-16f);
            float4 b4 = ((const float4*)bias)[lane + 32 * r];
            float4 o;
            o.x = fmaxf(acc[r][0] * inv + b4.x, 0.f);
            o.y = fmaxf(acc[r][1] * inv + b4.y, 0.f);
            o.z = fmaxf(acc[r][2] * inv + b4.z, 0.f);
            o.w = fmaxf(acc[r][3] * inv + b4.w, 0.f);
            ((float4*)out)[(size_t)n * (HC / 4) + lane + 32 * r] = o;
        }
    } else {
        // mean over heads: lane owns cols 4*lane..4*lane+3 of every head
        float v[4] = {0.f, 0.f, 0.f, 0.f};
#pragma unroll
        for (int r = 0; r < RV; r++) {
            float inv = 1.f / (ssum[r] + 1e-16f);
            v[0] += acc[r][0] * inv; v[1] += acc[r][1] * inv;
            v[2] += acc[r][2] * inv; v[3] += acc[r][3] * inv;
        }
        float4 b4 = ((const float4*)bias)[lane];
        float4 o;
        o.x = fmaxf(v[0] * 0.25f + b4.x, 0.f);
        o.y = fmaxf(v[1] * 0.25f + b4.y, 0.f);
        o.z = fmaxf(v[2] * 0.25f + b4.z, 0.f);
        o.w = fmaxf(v[3] * 0.25f + b4.w, 0.f);
        ((float4*)out)[(size_t)n * (OUT_ / 4) + lane] = o;
    }
}

// ---------------- pooling ----------------
__global__ void pool_accum_kernel(const float* __restrict__ h2,
                                  const int* __restrict__ batch)
{
    int n = blockIdx.x;
    int c = threadIdx.x;                  // 128
    int g = batch[n];
    atomicAdd(&g_gsum[g * OUT_ + c], h2[(size_t)n * OUT_ + c]);
    if (c == 0) atomicAdd(&g_gcnt[g], 1.f);
}

__global__ void pool_final_kernel(float* __restrict__ out) {
    int i = blockIdx.x * blockDim.x + threadIdx.x;   // G_*OUT_
    if (i >= G_ * OUT_) return;
    float cnt = fmaxf(g_gcnt[i / OUT_], 1.f);
    out[(size_t)N_ * OUT_ + i] = g_gsum[i] / cnt;
}

// ---------------- launcher ----------------
extern "C" void kernel_launch(void* const* d_in, const int* in_sizes, int n_in,
                              void* d_out, int out_size)
{
    const float* x       = (const float*)d_in[0];
    const float* eattr   = (const float*)d_in[1];
    const float* W1      = (const float*)d_in[2];
    const float* a_src1  = (const float*)d_in[3];
    const float* a_dst1  = (const float*)d_in[4];
    const float* We1     = (const float*)d_in[5];
    const float* a_edge1 = (const float*)d_in[6];
    const float* b1      = (const float*)d_in[7];
    const float* W2      = (const float*)d_in[8];
    const float* a_src2  = (const float*)d_in[9];
    const float* a_dst2  = (const float*)d_in[10];
    const float* We2     = (const float*)d_in[11];
    const float* a_edge2 = (const float*)d_in[12];
    const float* b2      = (const float*)d_in[13];
    const int*   eindex  = (const int*)d_in[14];
    const int*   batch   = (const int*)d_in[15];
    float* out = (float*)d_out;

    float *h1lin, *h1, *h2lin;
    cudaGetSymbolAddress((void**)&h1lin, g_h1lin);
    cudaGetSymbolAddress((void**)&h1,    g_h1);
    cudaGetSymbolAddress((void**)&h2lin, g_h2lin);
    float *as1p, *ad1p, *as2p, *ad2p, *ae1p, *ae2p;
    cudaGetSymbolAddress((void**)&as1p, g_as1);
    cudaGetSymbolAddress((void**)&ad1p, g_ad1);
    cudaGetSymbolAddress((void**)&as2p, g_as2);
    cudaGetSymbolAddress((void**)&ad2p, g_ad2);
    cudaGetSymbolAddress((void**)&ae1p, g_ae1);
    cudaGetSymbolAddress((void**)&ae2p, g_ae2);

    // 0) init
    zero_kernel<<<256, 256>>>();
    // 1) edge-attr mean + fold tiny matrices
    ea_sum_kernel<<<256, 256>>>(eattr);
    fold_v_kernel<<<1, 64>>>(We1, a_edge1, We2, a_edge2);
    // 2) CSR build (two-level scan)
    count_kernel<<<(ET_ + 255) / 256, 256>>>(eindex);
    scan_block_kernel<<<NB_, 256>>>();
    scan_tops_kernel<<<1, 128>>>();
    scan_finish_kernel<<<(N_ + 255) / 256, 256>>>();
    scatter_kernel<<<(ET_ + 255) / 256, 256>>>(eindex);
    // 3) per-edge scores (both layers)
    edge_scores_kernel<<<(ET_ + 255) / 256, 256>>>(eattr);
    // 4) layer 1
    {
        dim3 grid(HC1 / 128, (N_ + 127) / 128);
        sgemm_kernel<false><<<grid, 256>>>(x, W1, h1lin, N_, HC1, IN_);
    }
    node_scores_kernel<HC1, HID_>
        <<<(N_ * 32 + 255) / 256, 256>>>(h1lin, a_src1, a_dst1, as1p, ad1p);
    gat_aggregate_kernel<HC1, HID_, false>
        <<<(N_ * 32 + 255) / 256, 256>>>(h1lin, as1p, ad1p, ae1p, b1, h1);
    // 5) layer 2
    {
        dim3 grid(HC2 / 128, (N_ + 127) / 128);
        sgemm_kernel<true><<<grid, 256>>>(h1, W2, h2lin, N_, HC2, HC1);
    }
    node_scores_kernel<HC2, OUT_>
        <<<(N_ * 32 + 255) / 256, 256>>>(h2lin, a_src2, a_dst2, as2p, ad2p);
    gat_aggregate_kernel<HC2, OUT_, true>
        <<<(N_ * 32 + 255) / 256, 256>>>(h2lin, as2p, ad2p, ae2p, b2, out);
    // 6) graph pooling
    pool_accum_kernel<<<N_, OUT_>>>(out, batch);
    pool_final_kernel<<<(G_ * OUT_ + 255) / 256, 256>>>(out);
}